// round 14
// baseline (speedup 1.0000x reference)
#include <cuda_runtime.h>
#include <cuda_bf16.h>
#include <math.h>
#include <stdint.h>

// ---------------------------------------------------------------------------
// Problem constants
// ---------------------------------------------------------------------------
#define BATCH   2
#define SEQ     2048
#define DMODEL  1024
#define HEADS   16
#define DK      64
#define NTOK    (BATCH * SEQ)        // 4096

// ---------------------------------------------------------------------------
// Scratch (device globals — no allocation allowed)
// ---------------------------------------------------------------------------
__device__ __align__(256) float g_cos[SEQ * (DK / 2)];
__device__ __align__(256) float g_sin[SEQ * (DK / 2)];

// bf16 split operands
__device__ __align__(256) __nv_bfloat16 g_xhi[(size_t)NTOK * DMODEL];
__device__ __align__(256) __nv_bfloat16 g_xlo[(size_t)NTOK * DMODEL];
__device__ __align__(256) __nv_bfloat16 g_chi[(size_t)NTOK * DMODEL];
__device__ __align__(256) __nv_bfloat16 g_clo[(size_t)NTOK * DMODEL];
__device__ __align__(256) __nv_bfloat16 g_whi[4][(size_t)DMODEL * DMODEL];
__device__ __align__(256) __nv_bfloat16 g_wlo[4][(size_t)DMODEL * DMODEL];
// bf16 Q/K/V (written by GEMM epilogues, RoPE already applied to Q/K)
__device__ __align__(256) __nv_bfloat16 g_qhi[(size_t)NTOK * DMODEL];
__device__ __align__(256) __nv_bfloat16 g_qlo[(size_t)NTOK * DMODEL];
__device__ __align__(256) __nv_bfloat16 g_khi[(size_t)NTOK * DMODEL];
__device__ __align__(256) __nv_bfloat16 g_klo[(size_t)NTOK * DMODEL];
__device__ __align__(256) __nv_bfloat16 g_vhi[(size_t)NTOK * DMODEL];
__device__ __align__(256) __nv_bfloat16 g_vlo[(size_t)NTOK * DMODEL];

// ---------------------------------------------------------------------------
// Generic-PTX helpers (sm_80+/sm_75+; safe for compute_103 target)
// ---------------------------------------------------------------------------
__device__ __forceinline__ uint32_t smem_to_u32(const void* p) {
    uint32_t a;
    asm("{ .reg .u64 t; cvta.to.shared.u64 t, %1; cvt.u32.u64 %0, t; }" : "=r"(a) : "l"(p));
    return a;
}
__device__ __forceinline__ uint32_t swz128(uint32_t bo) { return bo ^ ((bo >> 3) & 0x70); }

__device__ __forceinline__ void cp16(uint32_t dst, const void* src) {
    asm volatile("cp.async.cg.shared.global [%0], [%1], 16;" :: "r"(dst), "l"(src) : "memory");
}
__device__ __forceinline__ void cp_commit() { asm volatile("cp.async.commit_group;" ::: "memory"); }
__device__ __forceinline__ void cp_wait1()  { asm volatile("cp.async.wait_group 1;"  ::: "memory"); }

__device__ __forceinline__ void ldsm4(uint32_t addr, uint32_t& r0, uint32_t& r1,
                                      uint32_t& r2, uint32_t& r3) {
    asm volatile("ldmatrix.sync.aligned.m8n8.x4.shared.b16 {%0,%1,%2,%3}, [%4];"
                 : "=r"(r0), "=r"(r1), "=r"(r2), "=r"(r3) : "r"(addr));
}
__device__ __forceinline__ void ldsm4t(uint32_t addr, uint32_t& r0, uint32_t& r1,
                                       uint32_t& r2, uint32_t& r3) {
    asm volatile("ldmatrix.sync.aligned.m8n8.x4.trans.shared.b16 {%0,%1,%2,%3}, [%4];"
                 : "=r"(r0), "=r"(r1), "=r"(r2), "=r"(r3) : "r"(addr));
}
__device__ __forceinline__ void mma16816(float& c0, float& c1, float& c2, float& c3,
                                         uint32_t a0, uint32_t a1, uint32_t a2, uint32_t a3,
                                         uint32_t b0, uint32_t b1) {
    asm volatile("mma.sync.aligned.m16n8k16.row.col.f32.bf16.bf16.f32 "
                 "{%0,%1,%2,%3}, {%4,%5,%6,%7}, {%8,%9}, {%0,%1,%2,%3};"
                 : "+f"(c0), "+f"(c1), "+f"(c2), "+f"(c3)
                 : "r"(a0), "r"(a1), "r"(a2), "r"(a3), "r"(b0), "r"(b1));
}
__device__ __forceinline__ uint32_t packbf(float x, float y) {
    __nv_bfloat162 t = __halves2bfloat162(__float2bfloat16_rn(x), __float2bfloat16_rn(y));
    return *reinterpret_cast<uint32_t*>(&t);
}

// ---------------------------------------------------------------------------
// RoPE table
// ---------------------------------------------------------------------------
__global__ void rope_table_kernel(float* __restrict__ cosT, float* __restrict__ sinT)
{
    int idx = blockIdx.x * blockDim.x + threadIdx.x;
    if (idx >= SEQ * (DK / 2)) return;
    int s = idx >> 5;
    int i = idx & 31;
    double inv = pow(10000.0, -((double)(2 * i) / (double)DK));
    float  invf = (float)inv;
    float  ang  = (float)s * invf;
    cosT[idx] = (float)cos((double)ang);
    sinT[idx] = (float)sin((double)ang);
}

// ---------------------------------------------------------------------------
// fp32 -> bf16 hi/lo split (for x and the four weights)
// ---------------------------------------------------------------------------
__global__ void split_bf16_kernel(const float* __restrict__ src,
                                  __nv_bfloat16* __restrict__ hi,
                                  __nv_bfloat16* __restrict__ lo, int n4)
{
    int i = blockIdx.x * blockDim.x + threadIdx.x;
    if (i >= n4) return;
    float4 a = ((const float4*)src)[i];
    __nv_bfloat16 h0 = __float2bfloat16_rn(a.x);
    __nv_bfloat16 h1 = __float2bfloat16_rn(a.y);
    __nv_bfloat16 h2 = __float2bfloat16_rn(a.z);
    __nv_bfloat16 h3 = __float2bfloat16_rn(a.w);
    __nv_bfloat16 l0 = __float2bfloat16_rn(a.x - __bfloat162float(h0));
    __nv_bfloat16 l1 = __float2bfloat16_rn(a.y - __bfloat162float(h1));
    __nv_bfloat16 l2 = __float2bfloat16_rn(a.z - __bfloat162float(h2));
    __nv_bfloat16 l3 = __float2bfloat16_rn(a.w - __bfloat162float(h3));
    __nv_bfloat162* hp = (__nv_bfloat162*)hi;
    __nv_bfloat162* lp = (__nv_bfloat162*)lo;
    hp[2 * i]     = __halves2bfloat162(h0, h1);
    hp[2 * i + 1] = __halves2bfloat162(h2, h3);
    lp[2 * i]     = __halves2bfloat162(l0, l1);
    lp[2 * i + 1] = __halves2bfloat162(l2, l3);
}

// ---------------------------------------------------------------------------
// mma.sync bf16-split GEMM:  C[M,N] = A[M,K] * B[N,K]^T  (hh + hl + lh)
// CTA 128x128, BK=64, SW128 smem, 2-stage cp.async pipeline.
// MODE 0: fp32 output. MODE 1: bf16 hi/lo + RoPE. MODE 2: bf16 hi/lo.
// ---------------------------------------------------------------------------
#define TM 128
#define TN 128
#define KC 64
#define NKC (DMODEL / KC)                 // 16
#define TILE_BYTES (TM * KC * 2)          // 16384
#define OFF_AHI 0
#define OFF_ALO (1 * TILE_BYTES)
#define OFF_BHI (2 * TILE_BYTES)
#define OFF_BLO (3 * TILE_BYTES)
#define STG_BYTES (4 * TILE_BYTES)        // 65536
#define GEMM_SMEM (2 * STG_BYTES)         // 131072

__device__ __forceinline__ void stage_load(
    const __nv_bfloat16* __restrict__ Ahi, const __nv_bfloat16* __restrict__ Alo,
    const __nv_bfloat16* __restrict__ Bhi, const __nv_bfloat16* __restrict__ Blo,
    int m0, int n0, int k0, uint32_t sbase, int tid)
{
#pragma unroll
    for (int i = 0; i < 4; ++i) {
        int v  = tid + i * 256;
        int r  = v >> 3;
        int c8 = v & 7;
        uint32_t sw = swz128((uint32_t)(r * 128 + c8 * 16));
        size_t goA = (size_t)(m0 + r) * DMODEL + k0 + c8 * 8;
        size_t goB = (size_t)(n0 + r) * DMODEL + k0 + c8 * 8;
        cp16(sbase + OFF_AHI + sw, Ahi + goA);
        cp16(sbase + OFF_ALO + sw, Alo + goA);
        cp16(sbase + OFF_BHI + sw, Bhi + goB);
        cp16(sbase + OFF_BLO + sw, Blo + goB);
    }
}

template<int MODE>
__global__ __launch_bounds__(256)
void gemm_mma_kernel(const __nv_bfloat16* __restrict__ Ahi, const __nv_bfloat16* __restrict__ Alo,
                     const __nv_bfloat16* __restrict__ Bhi, const __nv_bfloat16* __restrict__ Blo,
                     float* __restrict__ C,
                     __nv_bfloat16* __restrict__ Chi, __nv_bfloat16* __restrict__ Clo,
                     const float* __restrict__ cosT, const float* __restrict__ sinT)
{
    extern __shared__ char sm[];
    const uint32_t sb = smem_to_u32(sm);
    const int tid = threadIdx.x;
    const int wid = tid >> 5;
    const int lid = tid & 31;
    const int wm  = wid & 1;
    const int wn  = wid >> 1;
    const int m0c = blockIdx.y * TM;
    const int n0c = blockIdx.x * TN;
    const int mw  = wm * 64;
    const int nw  = wn * 32;

    float acc[4][4][4] = {};

    stage_load(Ahi, Alo, Bhi, Blo, m0c, n0c, 0, sb, tid);
    cp_commit();

    const int al  = lid & 15;
    const int ah  = lid >> 4;
    const int bl7 = lid & 7;
    const int bk  = (lid >> 3) & 1;
    const int bh8 = (lid >> 4) << 3;

    for (int kc = 0; kc < NKC; ++kc) {
        if (kc + 1 < NKC)
            stage_load(Ahi, Alo, Bhi, Blo, m0c, n0c, (kc + 1) * KC,
                       sb + ((kc + 1) & 1) * STG_BYTES, tid);
        cp_commit();
        cp_wait1();
        __syncthreads();

        const uint32_t base = sb + (kc & 1) * STG_BYTES;
#pragma unroll
        for (int c = 0; c < 4; ++c) {
            uint32_t bh[4][2], bl[4][2];
#pragma unroll
            for (int p = 0; p < 2; ++p) {
                int brow = nw + p * 16 + bl7 + bh8;
                uint32_t swo = swz128((uint32_t)(brow * 128 + c * 32 + bk * 16));
                uint32_t q0, q1, q2, q3;
                ldsm4(base + OFF_BHI + swo, q0, q1, q2, q3);
                bh[p*2][0] = q0; bh[p*2][1] = q1; bh[p*2+1][0] = q2; bh[p*2+1][1] = q3;
                ldsm4(base + OFF_BLO + swo, q0, q1, q2, q3);
                bl[p*2][0] = q0; bl[p*2][1] = q1; bl[p*2+1][0] = q2; bl[p*2+1][1] = q3;
            }
            uint32_t a[4][4];
#pragma unroll
            for (int mt = 0; mt < 4; ++mt) {
                int arow = mw + mt * 16 + al;
                uint32_t swo = swz128((uint32_t)(arow * 128 + c * 32 + ah * 16));
                ldsm4(base + OFF_AHI + swo, a[mt][0], a[mt][1], a[mt][2], a[mt][3]);
            }
#pragma unroll
            for (int mt = 0; mt < 4; ++mt)
#pragma unroll
                for (int nt = 0; nt < 4; ++nt) {
                    mma16816(acc[mt][nt][0], acc[mt][nt][1], acc[mt][nt][2], acc[mt][nt][3],
                             a[mt][0], a[mt][1], a[mt][2], a[mt][3], bh[nt][0], bh[nt][1]);
                    mma16816(acc[mt][nt][0], acc[mt][nt][1], acc[mt][nt][2], acc[mt][nt][3],
                             a[mt][0], a[mt][1], a[mt][2], a[mt][3], bl[nt][0], bl[nt][1]);
                }
#pragma unroll
            for (int mt = 0; mt < 4; ++mt) {
                int arow = mw + mt * 16 + al;
                uint32_t swo = swz128((uint32_t)(arow * 128 + c * 32 + ah * 16));
                ldsm4(base + OFF_ALO + swo, a[mt][0], a[mt][1], a[mt][2], a[mt][3]);
            }
#pragma unroll
            for (int mt = 0; mt < 4; ++mt)
#pragma unroll
                for (int nt = 0; nt < 4; ++nt)
                    mma16816(acc[mt][nt][0], acc[mt][nt][1], acc[mt][nt][2], acc[mt][nt][3],
                             a[mt][0], a[mt][1], a[mt][2], a[mt][3], bh[nt][0], bh[nt][1]);
        }
        __syncthreads();
    }

    // epilogue
    const int g   = lid >> 2;
    const int tig = lid & 3;
#pragma unroll
    for (int mt = 0; mt < 4; ++mt) {
        const int r0 = m0c + mw + mt * 16 + g;
        const int r1 = r0 + 8;
        const int pos0 = r0 & (SEQ - 1);
        const int pos1 = r1 & (SEQ - 1);
#pragma unroll
        for (int nt = 0; nt < 4; ++nt) {
            const int col = n0c + nw + nt * 8 + tig * 2;
            float d0 = acc[mt][nt][0], d1 = acc[mt][nt][1];
            float d2 = acc[mt][nt][2], d3 = acc[mt][nt][3];
            if (MODE == 1) {
                const int p = (col & 63) >> 1;
                float c0 = cosT[pos0 * 32 + p], s0 = sinT[pos0 * 32 + p];
                float c1 = cosT[pos1 * 32 + p], s1 = sinT[pos1 * 32 + p];
                float x = d0, y = d1;
                d0 = x * c0 - y * s0;  d1 = y * c0 + x * s0;
                x = d2; y = d3;
                d2 = x * c1 - y * s1;  d3 = y * c1 + x * s1;
            }
            if (MODE == 0) {
                *(float2*)(C + (size_t)r0 * DMODEL + col) = make_float2(d0, d1);
                *(float2*)(C + (size_t)r1 * DMODEL + col) = make_float2(d2, d3);
            } else {
                uint32_t h0 = packbf(d0, d1);
                uint32_t h1 = packbf(d2, d3);
                float e0 = d0 - __bfloat162float(*(__nv_bfloat16*)&h0);
                float e1 = d1 - __bfloat162float(((__nv_bfloat16*)&h0)[1]);
                float e2 = d2 - __bfloat162float(*(__nv_bfloat16*)&h1);
                float e3 = d3 - __bfloat162float(((__nv_bfloat16*)&h1)[1]);
                *(uint32_t*)(Chi + (size_t)r0 * DMODEL + col) = h0;
                *(uint32_t*)(Chi + (size_t)r1 * DMODEL + col) = h1;
                *(uint32_t*)(Clo + (size_t)r0 * DMODEL + col) = packbf(e0, e1);
                *(uint32_t*)(Clo + (size_t)r1 * DMODEL + col) = packbf(e2, e3);
            }
        }
    }
}

// ---------------------------------------------------------------------------
// Tensor-core flash attention (causal), bf16-split, mma.sync.
// CTA: 128 Q rows x one (b,h). 8 warps x 16 Q rows. K/V tiles of 64 rows.
// smem: Qhi/Qlo (32KB one-time) + 2-stage KV (2 x 32KB) = 96KB.
// ---------------------------------------------------------------------------
#define AO_QHI 0
#define AO_QLO 16384
#define AO_KV  32768
#define AKT    8192                    // one 64x64 bf16 tile
#define AST    (4 * AKT)               // Khi,Klo,Vhi,Vlo per stage = 32768
#define ATTN_SMEM (AO_KV + 2 * AST)    // 98304

__device__ __forceinline__ void attn_load_kv(
    const __nv_bfloat16* __restrict__ khi, const __nv_bfloat16* __restrict__ klo,
    const __nv_bfloat16* __restrict__ vhi, const __nv_bfloat16* __restrict__ vlo,
    size_t hbase, int kv0, uint32_t dst, int tid)
{
#pragma unroll
    for (int i = 0; i < 2; ++i) {
        int v  = tid + i * 256;
        int r  = v >> 3;
        int c8 = v & 7;
        uint32_t sw = swz128((uint32_t)(r * 128 + c8 * 16));
        size_t go = hbase + (size_t)(kv0 + r) * DMODEL + c8 * 8;
        cp16(dst + 0 * AKT + sw, khi + go);
        cp16(dst + 1 * AKT + sw, klo + go);
        cp16(dst + 2 * AKT + sw, vhi + go);
        cp16(dst + 3 * AKT + sw, vlo + go);
    }
}

__global__ __launch_bounds__(256, 1)
void attn_tc_kernel(const __nv_bfloat16* __restrict__ qhi, const __nv_bfloat16* __restrict__ qlo,
                    const __nv_bfloat16* __restrict__ khi, const __nv_bfloat16* __restrict__ klo,
                    const __nv_bfloat16* __restrict__ vhi, const __nv_bfloat16* __restrict__ vlo,
                    __nv_bfloat16* __restrict__ Ohi, __nv_bfloat16* __restrict__ Olo)
{
    extern __shared__ char sm[];
    const uint32_t sb = smem_to_u32(sm);
    const int tid = threadIdx.x;
    const int wid = tid >> 5;
    const int lid = tid & 31;
    const int qt  = (int)gridDim.x - 1 - (int)blockIdx.x;   // heavy tiles first
    const int bh  = blockIdx.y;
    const int b   = bh >> 4;
    const int h   = bh & 15;
    const int q0  = qt * 128;
    const int qbase = q0 + wid * 16;

    const size_t hbase = (size_t)b * SEQ * DMODEL + (size_t)h * DK;

    // stage Q (group 0)
#pragma unroll
    for (int i = 0; i < 4; ++i) {
        int v = tid + i * 256;
        int r = v >> 3;
        int c8 = v & 7;
        uint32_t sw = swz128((uint32_t)(r * 128 + c8 * 16));
        size_t go = hbase + (size_t)(q0 + r) * DMODEL + c8 * 8;
        cp16(sb + AO_QHI + sw, qhi + go);
        cp16(sb + AO_QLO + sw, qlo + go);
    }
    cp_commit();
    // stage KV ktile 0 (group 1)
    attn_load_kv(khi, klo, vhi, vlo, hbase, 0, sb + AO_KV, tid);
    cp_commit();

    cp_wait1();            // Q resident
    __syncthreads();

    // Q fragments (A-frag, per k16 chunk)
    const int al  = lid & 15;
    const int ah  = lid >> 4;
    uint32_t Qh[4][4], Ql[4][4];
#pragma unroll
    for (int c = 0; c < 4; ++c) {
        uint32_t swo = swz128((uint32_t)((wid * 16 + al) * 128 + c * 32 + ah * 16));
        ldsm4(sb + AO_QHI + swo, Qh[c][0], Qh[c][1], Qh[c][2], Qh[c][3]);
        ldsm4(sb + AO_QLO + swo, Ql[c][0], Ql[c][1], Ql[c][2], Ql[c][3]);
    }

    const int g   = lid >> 2;
    const int tig = lid & 3;
    const int bl7 = lid & 7;
    const int bk  = (lid >> 3) & 1;
    const int bh8 = (lid >> 4) << 3;
    const int r0g = qbase + g;
    const int r1g = r0g + 8;

    float m0 = -1e30f, m1 = -1e30f, l0 = 0.f, l1 = 0.f;
    float o[8][4] = {};

    const int NT = 2 * qt + 2;
    for (int kt = 0; kt < NT; ++kt) {
        const int kv0 = kt * 64;
        if (kt + 1 < NT)
            attn_load_kv(khi, klo, vhi, vlo, hbase, (kt + 1) * 64,
                         sb + AO_KV + ((kt + 1) & 1) * AST, tid);
        cp_commit();
        cp_wait1();
        __syncthreads();

        if (kv0 <= qbase + 15) {        // tile touches valid region for this warp
            const uint32_t base = sb + AO_KV + (kt & 1) * AST;

            // ---- S = Q K^T (3-term split) ----
            float s[8][4] = {};
#pragma unroll
            for (int c = 0; c < 4; ++c) {
#pragma unroll
                for (int p = 0; p < 4; ++p) {
                    int brow = p * 16 + bl7 + bh8;
                    uint32_t swo = swz128((uint32_t)(brow * 128 + c * 32 + bk * 16));
                    uint32_t h0, h1, h2, h3, e0, e1, e2, e3;
                    ldsm4(base + 0 * AKT + swo, h0, h1, h2, h3);
                    ldsm4(base + 1 * AKT + swo, e0, e1, e2, e3);
                    const int n0 = 2 * p, n1 = 2 * p + 1;
                    mma16816(s[n0][0], s[n0][1], s[n0][2], s[n0][3],
                             Qh[c][0], Qh[c][1], Qh[c][2], Qh[c][3], h0, h1);
                    mma16816(s[n0][0], s[n0][1], s[n0][2], s[n0][3],
                             Qh[c][0], Qh[c][1], Qh[c][2], Qh[c][3], e0, e1);
                    mma16816(s[n0][0], s[n0][1], s[n0][2], s[n0][3],
                             Ql[c][0], Ql[c][1], Ql[c][2], Ql[c][3], h0, h1);
                    mma16816(s[n1][0], s[n1][1], s[n1][2], s[n1][3],
                             Qh[c][0], Qh[c][1], Qh[c][2], Qh[c][3], h2, h3);
                    mma16816(s[n1][0], s[n1][1], s[n1][2], s[n1][3],
                             Qh[c][0], Qh[c][1], Qh[c][2], Qh[c][3], e2, e3);
                    mma16816(s[n1][0], s[n1][1], s[n1][2], s[n1][3],
                             Ql[c][0], Ql[c][1], Ql[c][2], Ql[c][3], h2, h3);
                }
            }
            // scale
#pragma unroll
            for (int nt = 0; nt < 8; ++nt)
#pragma unroll
                for (int j = 0; j < 4; ++j) s[nt][j] *= 0.125f;

            // causal mask (only near-diagonal tiles)
            if (kv0 + 63 > qbase) {
#pragma unroll
                for (int nt = 0; nt < 8; ++nt) {
                    const int c0 = kv0 + nt * 8 + tig * 2;
                    if (c0     > r0g) s[nt][0] = -1e30f;
                    if (c0 + 1 > r0g) s[nt][1] = -1e30f;
                    if (c0     > r1g) s[nt][2] = -1e30f;
                    if (c0 + 1 > r1g) s[nt][3] = -1e30f;
                }
            }

            // ---- online softmax ----
            float rm0 = -1e30f, rm1 = -1e30f;
#pragma unroll
            for (int nt = 0; nt < 8; ++nt) {
                rm0 = fmaxf(rm0, fmaxf(s[nt][0], s[nt][1]));
                rm1 = fmaxf(rm1, fmaxf(s[nt][2], s[nt][3]));
            }
            rm0 = fmaxf(rm0, __shfl_xor_sync(0xffffffffu, rm0, 1));
            rm0 = fmaxf(rm0, __shfl_xor_sync(0xffffffffu, rm0, 2));
            rm1 = fmaxf(rm1, __shfl_xor_sync(0xffffffffu, rm1, 1));
            rm1 = fmaxf(rm1, __shfl_xor_sync(0xffffffffu, rm1, 2));
            const float mn0 = fmaxf(m0, rm0);
            const float mn1 = fmaxf(m1, rm1);
            const float a0  = __expf(m0 - mn0);
            const float a1  = __expf(m1 - mn1);
            float rs0 = 0.f, rs1 = 0.f;
#pragma unroll
            for (int nt = 0; nt < 8; ++nt) {
                s[nt][0] = __expf(s[nt][0] - mn0);
                s[nt][1] = __expf(s[nt][1] - mn0);
                s[nt][2] = __expf(s[nt][2] - mn1);
                s[nt][3] = __expf(s[nt][3] - mn1);
                rs0 += s[nt][0] + s[nt][1];
                rs1 += s[nt][2] + s[nt][3];
            }
            rs0 += __shfl_xor_sync(0xffffffffu, rs0, 1);
            rs0 += __shfl_xor_sync(0xffffffffu, rs0, 2);
            rs1 += __shfl_xor_sync(0xffffffffu, rs1, 1);
            rs1 += __shfl_xor_sync(0xffffffffu, rs1, 2);
            l0 = l0 * a0 + rs0;  m0 = mn0;
            l1 = l1 * a1 + rs1;  m1 = mn1;
#pragma unroll
            for (int nt = 0; nt < 8; ++nt) {
                o[nt][0] *= a0; o[nt][1] *= a0;
                o[nt][2] *= a1; o[nt][3] *= a1;
            }

            // ---- pack P (hi/lo) into A-fragments ----
            uint32_t ph[8][2], pl[8][2];
#pragma unroll
            for (int nt = 0; nt < 8; ++nt) {
                ph[nt][0] = packbf(s[nt][0], s[nt][1]);
                ph[nt][1] = packbf(s[nt][2], s[nt][3]);
                float e0 = s[nt][0] - __bfloat162float(*(__nv_bfloat16*)&ph[nt][0]);
                float e1 = s[nt][1] - __bfloat162float(((__nv_bfloat16*)&ph[nt][0])[1]);
                float e2 = s[nt][2] - __bfloat162float(*(__nv_bfloat16*)&ph[nt][1]);
                float e3 = s[nt][3] - __bfloat162float(((__nv_bfloat16*)&ph[nt][1])[1]);
                pl[nt][0] = packbf(e0, e1);
                pl[nt][1] = packbf(e2, e3);
            }

            // ---- O += P V (3-term split), V via ldmatrix.trans ----
#pragma unroll
            for (int c = 0; c < 4; ++c) {
                const uint32_t A0 = ph[2*c][0],   A1 = ph[2*c][1];
                const uint32_t A2 = ph[2*c+1][0], A3 = ph[2*c+1][1];
                const uint32_t L0 = pl[2*c][0],   L1 = pl[2*c][1];
                const uint32_t L2 = pl[2*c+1][0], L3 = pl[2*c+1][1];
#pragma unroll
                for (int p = 0; p < 4; ++p) {
                    int krow = c * 16 + bl7 + bk * 8;
                    int ncol = p * 16 + (lid >> 4) * 8;
                    uint32_t swo = swz128((uint32_t)(krow * 128 + ncol * 2));
                    uint32_t h0, h1, h2, h3, e0, e1, e2, e3;
                    ldsm4t(base + 2 * AKT + swo, h0, h1, h2, h3);
                    ldsm4t(base + 3 * AKT + swo, e0, e1, e2, e3);
                    const int n0 = 2 * p, n1 = 2 * p + 1;
                    mma16816(o[n0][0], o[n0][1], o[n0][2], o[n0][3],
                             A0, A1, A2, A3, h0, h1);
                    mma16816(o[n0][0], o[n0][1], o[n0][2], o[n0][3],
                             A0, A1, A2, A3, e0, e1);
                    mma16816(o[n0][0], o[n0][1], o[n0][2], o[n0][3],
                             L0, L1, L2, L3, h0, h1);
                    mma16816(o[n1][0], o[n1][1], o[n1][2], o[n1][3],
                             A0, A1, A2, A3, h2, h3);
                    mma16816(o[n1][0], o[n1][1], o[n1][2], o[n1][3],
                             A0, A1, A2, A3, e2, e3);
                    mma16816(o[n1][0], o[n1][1], o[n1][2], o[n1][3],
                             L0, L1, L2, L3, h2, h3);
                }
            }
        }
        __syncthreads();
    }

    // ---- finalize: normalize, split to bf16 hi/lo context ----
    const float inv0 = 1.f / l0;
    const float inv1 = 1.f / l1;
#pragma unroll
    for (int nt = 0; nt < 8; ++nt) {
        const int col = nt * 8 + tig * 2;
        float d0 = o[nt][0] * inv0, d1 = o[nt][1] * inv0;
        float d2 = o[nt][2] * inv1, d3 = o[nt][3] * inv1;
        uint32_t h0 = packbf(d0, d1);
        uint32_t h1 = packbf(d2, d3);
        float e0 = d0 - __bfloat162float(*(__nv_bfloat16*)&h0);
        float e1 = d1 - __bfloat162float(((__nv_bfloat16*)&h0)[1]);
        float e2 = d2 - __bfloat162float(*(__nv_bfloat16*)&h1);
        float e3 = d3 - __bfloat162float(((__nv_bfloat16*)&h1)[1]);
        *(uint32_t*)(Ohi + hbase + (size_t)r0g * DMODEL + col) = h0;
        *(uint32_t*)(Ohi + hbase + (size_t)r1g * DMODEL + col) = h1;
        *(uint32_t*)(Olo + hbase + (size_t)r0g * DMODEL + col) = packbf(e0, e1);
        *(uint32_t*)(Olo + hbase + (size_t)r1g * DMODEL + col) = packbf(e2, e3);
    }
}

// ---------------------------------------------------------------------------
// Launch
// ---------------------------------------------------------------------------
extern "C" void kernel_launch(void* const* d_in, const int* in_sizes, int n_in,
                              void* d_out, int out_size)
{
    const float* x  = (const float*)d_in[0];
    const float* wq = (const float*)d_in[1];
    const float* wk = (const float*)d_in[2];
    const float* wv = (const float*)d_in[3];
    const float* wo = (const float*)d_in[4];
    float* out = (float*)d_out;

    float *cT, *sT;
    cudaGetSymbolAddress((void**)&cT, g_cos);
    cudaGetSymbolAddress((void**)&sT, g_sin);

    __nv_bfloat16 *xhi, *xlo, *chi, *clo, *whi, *wlo;
    __nv_bfloat16 *qh, *ql, *kh, *kl, *vh, *vl;
    cudaGetSymbolAddress((void**)&xhi, g_xhi);
    cudaGetSymbolAddress((void**)&xlo, g_xlo);
    cudaGetSymbolAddress((void**)&chi, g_chi);
    cudaGetSymbolAddress((void**)&clo, g_clo);
    cudaGetSymbolAddress((void**)&whi, g_whi);
    cudaGetSymbolAddress((void**)&wlo, g_wlo);
    cudaGetSymbolAddress((void**)&qh,  g_qhi);
    cudaGetSymbolAddress((void**)&ql,  g_qlo);
    cudaGetSymbolAddress((void**)&kh,  g_khi);
    cudaGetSymbolAddress((void**)&kl,  g_klo);
    cudaGetSymbolAddress((void**)&vh,  g_vhi);
    cudaGetSymbolAddress((void**)&vl,  g_vlo);
    const size_t WN = (size_t)DMODEL * DMODEL;

    cudaFuncSetAttribute(gemm_mma_kernel<0>,
                         cudaFuncAttributeMaxDynamicSharedMemorySize, GEMM_SMEM);
    cudaFuncSetAttribute(gemm_mma_kernel<1>,
                         cudaFuncAttributeMaxDynamicSharedMemorySize, GEMM_SMEM);
    cudaFuncSetAttribute(gemm_mma_kernel<2>,
                         cudaFuncAttributeMaxDynamicSharedMemorySize, GEMM_SMEM);
    cudaFuncSetAttribute(attn_tc_kernel,
                         cudaFuncAttributeMaxDynamicSharedMemorySize, ATTN_SMEM);

    rope_table_kernel<<<(SEQ * 32 + 255) / 256, 256>>>(cT, sT);

    const int xN4 = NTOK * DMODEL / 4;
    const int wN4 = DMODEL * DMODEL / 4;
    split_bf16_kernel<<<(xN4 + 255) / 256, 256>>>(x,  xhi, xlo, xN4);
    split_bf16_kernel<<<(wN4 + 255) / 256, 256>>>(wq, whi + 0 * WN, wlo + 0 * WN, wN4);
    split_bf16_kernel<<<(wN4 + 255) / 256, 256>>>(wk, whi + 1 * WN, wlo + 1 * WN, wN4);
    split_bf16_kernel<<<(wN4 + 255) / 256, 256>>>(wv, whi + 2 * WN, wlo + 2 * WN, wN4);
    split_bf16_kernel<<<(wN4 + 255) / 256, 256>>>(wo, whi + 3 * WN, wlo + 3 * WN, wN4);

    dim3 gg(DMODEL / TN, NTOK / TM);   // (8, 32)
    gemm_mma_kernel<1><<<gg, 256, GEMM_SMEM>>>(xhi, xlo, whi + 0 * WN, wlo + 0 * WN,
                                               nullptr, qh, ql, cT, sT);
    gemm_mma_kernel<1><<<gg, 256, GEMM_SMEM>>>(xhi, xlo, whi + 1 * WN, wlo + 1 * WN,
                                               nullptr, kh, kl, cT, sT);
    gemm_mma_kernel<2><<<gg, 256, GEMM_SMEM>>>(xhi, xlo, whi + 2 * WN, wlo + 2 * WN,
                                               nullptr, vh, vl, cT, sT);

    attn_tc_kernel<<<dim3(SEQ / 128, BATCH * HEADS), 256, ATTN_SMEM>>>(
        qh, ql, kh, kl, vh, vl, chi, clo);

    gemm_mma_kernel<0><<<gg, 256, GEMM_SMEM>>>(chi, clo, whi + 3 * WN, wlo + 3 * WN,
                                               out, nullptr, nullptr, cT, sT);
}

// round 15
// speedup vs baseline: 1.0247x; 1.0247x over previous
#include <cuda_runtime.h>
#include <cuda_bf16.h>
#include <math.h>
#include <stdint.h>

// ---------------------------------------------------------------------------
// Problem constants
// ---------------------------------------------------------------------------
#define BATCH   2
#define SEQ     2048
#define DMODEL  1024
#define HEADS   16
#define DK      64
#define NTOK    (BATCH * SEQ)        // 4096

// ---------------------------------------------------------------------------
// Scratch (device globals — no allocation allowed)
// ---------------------------------------------------------------------------
__device__ __align__(256) float g_cos[SEQ * (DK / 2)];
__device__ __align__(256) float g_sin[SEQ * (DK / 2)];

__device__ __align__(256) __nv_bfloat16 g_xhi[(size_t)NTOK * DMODEL];
__device__ __align__(256) __nv_bfloat16 g_xlo[(size_t)NTOK * DMODEL];
__device__ __align__(256) __nv_bfloat16 g_chi[(size_t)NTOK * DMODEL];
__device__ __align__(256) __nv_bfloat16 g_clo[(size_t)NTOK * DMODEL];
__device__ __align__(256) __nv_bfloat16 g_whi[4][(size_t)DMODEL * DMODEL];
__device__ __align__(256) __nv_bfloat16 g_wlo[4][(size_t)DMODEL * DMODEL];
__device__ __align__(256) __nv_bfloat16 g_qhi[(size_t)NTOK * DMODEL];
__device__ __align__(256) __nv_bfloat16 g_qlo[(size_t)NTOK * DMODEL];
__device__ __align__(256) __nv_bfloat16 g_khi[(size_t)NTOK * DMODEL];
__device__ __align__(256) __nv_bfloat16 g_klo[(size_t)NTOK * DMODEL];
__device__ __align__(256) __nv_bfloat16 g_vhi[(size_t)NTOK * DMODEL];
__device__ __align__(256) __nv_bfloat16 g_vlo[(size_t)NTOK * DMODEL];

// ---------------------------------------------------------------------------
// Generic-PTX helpers (sm_80+/sm_75+; safe for compute_103 target)
// ---------------------------------------------------------------------------
__device__ __forceinline__ uint32_t smem_to_u32(const void* p) {
    uint32_t a;
    asm("{ .reg .u64 t; cvta.to.shared.u64 t, %1; cvt.u32.u64 %0, t; }" : "=r"(a) : "l"(p));
    return a;
}
__device__ __forceinline__ uint32_t swz128(uint32_t bo) { return bo ^ ((bo >> 3) & 0x70); }

__device__ __forceinline__ void cp16(uint32_t dst, const void* src) {
    asm volatile("cp.async.cg.shared.global [%0], [%1], 16;" :: "r"(dst), "l"(src) : "memory");
}
__device__ __forceinline__ void cp_commit() { asm volatile("cp.async.commit_group;" ::: "memory"); }
__device__ __forceinline__ void cp_wait1()  { asm volatile("cp.async.wait_group 1;"  ::: "memory"); }

__device__ __forceinline__ void ldsm4(uint32_t addr, uint32_t& r0, uint32_t& r1,
                                      uint32_t& r2, uint32_t& r3) {
    asm volatile("ldmatrix.sync.aligned.m8n8.x4.shared.b16 {%0,%1,%2,%3}, [%4];"
                 : "=r"(r0), "=r"(r1), "=r"(r2), "=r"(r3) : "r"(addr));
}
__device__ __forceinline__ void ldsm4t(uint32_t addr, uint32_t& r0, uint32_t& r1,
                                       uint32_t& r2, uint32_t& r3) {
    asm volatile("ldmatrix.sync.aligned.m8n8.x4.trans.shared.b16 {%0,%1,%2,%3}, [%4];"
                 : "=r"(r0), "=r"(r1), "=r"(r2), "=r"(r3) : "r"(addr));
}
__device__ __forceinline__ void mma16816(float& c0, float& c1, float& c2, float& c3,
                                         uint32_t a0, uint32_t a1, uint32_t a2, uint32_t a3,
                                         uint32_t b0, uint32_t b1) {
    asm volatile("mma.sync.aligned.m16n8k16.row.col.f32.bf16.bf16.f32 "
                 "{%0,%1,%2,%3}, {%4,%5,%6,%7}, {%8,%9}, {%0,%1,%2,%3};"
                 : "+f"(c0), "+f"(c1), "+f"(c2), "+f"(c3)
                 : "r"(a0), "r"(a1), "r"(a2), "r"(a3), "r"(b0), "r"(b1));
}
__device__ __forceinline__ uint32_t packbf(float x, float y) {
    __nv_bfloat162 t = __halves2bfloat162(__float2bfloat16_rn(x), __float2bfloat16_rn(y));
    return *reinterpret_cast<uint32_t*>(&t);
}

// ---------------------------------------------------------------------------
// RoPE table
// ---------------------------------------------------------------------------
__global__ void rope_table_kernel(float* __restrict__ cosT, float* __restrict__ sinT)
{
    int idx = blockIdx.x * blockDim.x + threadIdx.x;
    if (idx >= SEQ * (DK / 2)) return;
    int s = idx >> 5;
    int i = idx & 31;
    double inv = pow(10000.0, -((double)(2 * i) / (double)DK));
    float  invf = (float)inv;
    float  ang  = (float)s * invf;
    cosT[idx] = (float)cos((double)ang);
    sinT[idx] = (float)sin((double)ang);
}

// ---------------------------------------------------------------------------
// fp32 -> bf16 hi/lo split (single src)
// ---------------------------------------------------------------------------
__device__ __forceinline__ void split4(const float* __restrict__ src,
                                       __nv_bfloat16* __restrict__ hi,
                                       __nv_bfloat16* __restrict__ lo, int i)
{
    float4 a = ((const float4*)src)[i];
    __nv_bfloat16 h0 = __float2bfloat16_rn(a.x);
    __nv_bfloat16 h1 = __float2bfloat16_rn(a.y);
    __nv_bfloat16 h2 = __float2bfloat16_rn(a.z);
    __nv_bfloat16 h3 = __float2bfloat16_rn(a.w);
    __nv_bfloat16 l0 = __float2bfloat16_rn(a.x - __bfloat162float(h0));
    __nv_bfloat16 l1 = __float2bfloat16_rn(a.y - __bfloat162float(h1));
    __nv_bfloat16 l2 = __float2bfloat16_rn(a.z - __bfloat162float(h2));
    __nv_bfloat16 l3 = __float2bfloat16_rn(a.w - __bfloat162float(h3));
    __nv_bfloat162* hp = (__nv_bfloat162*)hi;
    __nv_bfloat162* lp = (__nv_bfloat162*)lo;
    hp[2 * i]     = __halves2bfloat162(h0, h1);
    hp[2 * i + 1] = __halves2bfloat162(h2, h3);
    lp[2 * i]     = __halves2bfloat162(l0, l1);
    lp[2 * i + 1] = __halves2bfloat162(l2, l3);
}

__global__ void split_bf16_kernel(const float* __restrict__ src,
                                  __nv_bfloat16* __restrict__ hi,
                                  __nv_bfloat16* __restrict__ lo, int n4)
{
    int i = blockIdx.x * blockDim.x + threadIdx.x;
    if (i < n4) split4(src, hi, lo, i);
}

// All four weights in one launch (blockIdx.y selects the matrix)
__global__ void split_w4_kernel(const float* __restrict__ w0, const float* __restrict__ w1,
                                const float* __restrict__ w2, const float* __restrict__ w3,
                                __nv_bfloat16* __restrict__ hi, __nv_bfloat16* __restrict__ lo,
                                int n4)
{
    int i = blockIdx.x * blockDim.x + threadIdx.x;
    if (i >= n4) return;
    const float* src = (blockIdx.y == 0) ? w0 : (blockIdx.y == 1) ? w1
                      : (blockIdx.y == 2) ? w2 : w3;
    size_t off = (size_t)blockIdx.y * DMODEL * DMODEL;
    split4(src, hi + off, lo + off, i);
}

// ---------------------------------------------------------------------------
// mma.sync bf16-split GEMM:  C[M,N] = A[M,K] * B[N,K]^T  (hh + hl + lh)
// CTA 128x256, BK=64, SW128 smem, 2-stage cp.async pipeline. 128 CTAs = 1 wave.
// 8 warps as 2(M) x 4(N); warp tile 64x64 = 4x8 m16n8 accum tiles.
// MODE 0: fp32 output. MODE 1: bf16 hi/lo + RoPE. MODE 2: bf16 hi/lo.
// ---------------------------------------------------------------------------
#define TM 128
#define TN 256
#define KC 64
#define NKC (DMODEL / KC)                 // 16
#define A_TB (TM * KC * 2)                // 16384
#define B_TB (TN * KC * 2)                // 32768
#define OFF_AHI 0
#define OFF_ALO (A_TB)
#define OFF_BHI (2 * A_TB)
#define OFF_BLO (2 * A_TB + B_TB)
#define STG_BYTES (2 * A_TB + 2 * B_TB)   // 98304
#define GEMM_SMEM (2 * STG_BYTES)         // 196608

__device__ __forceinline__ void stage_load(
    const __nv_bfloat16* __restrict__ Ahi, const __nv_bfloat16* __restrict__ Alo,
    const __nv_bfloat16* __restrict__ Bhi, const __nv_bfloat16* __restrict__ Blo,
    int m0, int n0, int k0, uint32_t sbase, int tid)
{
#pragma unroll
    for (int i = 0; i < 4; ++i) {          // A: 1024 vectors
        int v  = tid + i * 256;
        int r  = v >> 3;
        int c8 = v & 7;
        uint32_t sw = swz128((uint32_t)(r * 128 + c8 * 16));
        size_t go = (size_t)(m0 + r) * DMODEL + k0 + c8 * 8;
        cp16(sbase + OFF_AHI + sw, Ahi + go);
        cp16(sbase + OFF_ALO + sw, Alo + go);
    }
#pragma unroll
    for (int i = 0; i < 8; ++i) {          // B: 2048 vectors
        int v  = tid + i * 256;
        int r  = v >> 3;
        int c8 = v & 7;
        uint32_t sw = swz128((uint32_t)(r * 128 + c8 * 16));
        size_t go = (size_t)(n0 + r) * DMODEL + k0 + c8 * 8;
        cp16(sbase + OFF_BHI + sw, Bhi + go);
        cp16(sbase + OFF_BLO + sw, Blo + go);
    }
}

template<int MODE>
__global__ __launch_bounds__(256, 1)
void gemm_mma_kernel(const __nv_bfloat16* __restrict__ Ahi, const __nv_bfloat16* __restrict__ Alo,
                     const __nv_bfloat16* __restrict__ Bhi, const __nv_bfloat16* __restrict__ Blo,
                     float* __restrict__ C,
                     __nv_bfloat16* __restrict__ Chi, __nv_bfloat16* __restrict__ Clo,
                     const float* __restrict__ cosT, const float* __restrict__ sinT)
{
    extern __shared__ char sm[];
    const uint32_t sb = smem_to_u32(sm);
    const int tid = threadIdx.x;
    const int wid = tid >> 5;
    const int lid = tid & 31;
    const int mw  = (wid & 1) * 64;       // 2 warps in M
    const int nw  = (wid >> 1) * 64;      // 4 warps in N
    const int m0c = blockIdx.y * TM;
    const int n0c = blockIdx.x * TN;

    float acc[4][8][4] = {};

    stage_load(Ahi, Alo, Bhi, Blo, m0c, n0c, 0, sb, tid);
    cp_commit();

    const int al  = lid & 15;
    const int ah  = lid >> 4;
    const int bl7 = lid & 7;
    const int bk  = (lid >> 3) & 1;
    const int bh8 = (lid >> 4) << 3;

    for (int kc = 0; kc < NKC; ++kc) {
        if (kc + 1 < NKC)
            stage_load(Ahi, Alo, Bhi, Blo, m0c, n0c, (kc + 1) * KC,
                       sb + ((kc + 1) & 1) * STG_BYTES, tid);
        cp_commit();
        cp_wait1();
        __syncthreads();

        const uint32_t base = sb + (kc & 1) * STG_BYTES;
#pragma unroll
        for (int c = 0; c < 4; ++c) {
            uint32_t bh[8][2], bl[8][2];
#pragma unroll
            for (int p = 0; p < 4; ++p) {          // 4 pairs of n8 tiles
                int brow = nw + p * 16 + bl7 + bh8;
                uint32_t swo = swz128((uint32_t)(brow * 128 + c * 32 + bk * 16));
                uint32_t q0, q1, q2, q3;
                ldsm4(base + OFF_BHI + swo, q0, q1, q2, q3);
                bh[p*2][0] = q0; bh[p*2][1] = q1; bh[p*2+1][0] = q2; bh[p*2+1][1] = q3;
                ldsm4(base + OFF_BLO + swo, q0, q1, q2, q3);
                bl[p*2][0] = q0; bl[p*2][1] = q1; bl[p*2+1][0] = q2; bl[p*2+1][1] = q3;
            }
            uint32_t a[4][4];
#pragma unroll
            for (int mt = 0; mt < 4; ++mt) {
                int arow = mw + mt * 16 + al;
                uint32_t swo = swz128((uint32_t)(arow * 128 + c * 32 + ah * 16));
                ldsm4(base + OFF_AHI + swo, a[mt][0], a[mt][1], a[mt][2], a[mt][3]);
            }
#pragma unroll
            for (int mt = 0; mt < 4; ++mt)
#pragma unroll
                for (int nt = 0; nt < 8; ++nt) {
                    mma16816(acc[mt][nt][0], acc[mt][nt][1], acc[mt][nt][2], acc[mt][nt][3],
                             a[mt][0], a[mt][1], a[mt][2], a[mt][3], bh[nt][0], bh[nt][1]);
                    mma16816(acc[mt][nt][0], acc[mt][nt][1], acc[mt][nt][2], acc[mt][nt][3],
                             a[mt][0], a[mt][1], a[mt][2], a[mt][3], bl[nt][0], bl[nt][1]);
                }
#pragma unroll
            for (int mt = 0; mt < 4; ++mt) {
                int arow = mw + mt * 16 + al;
                uint32_t swo = swz128((uint32_t)(arow * 128 + c * 32 + ah * 16));
                ldsm4(base + OFF_ALO + swo, a[mt][0], a[mt][1], a[mt][2], a[mt][3]);
            }
#pragma unroll
            for (int mt = 0; mt < 4; ++mt)
#pragma unroll
                for (int nt = 0; nt < 8; ++nt)
                    mma16816(acc[mt][nt][0], acc[mt][nt][1], acc[mt][nt][2], acc[mt][nt][3],
                             a[mt][0], a[mt][1], a[mt][2], a[mt][3], bh[nt][0], bh[nt][1]);
        }
        __syncthreads();
    }

    // epilogue
    const int g   = lid >> 2;
    const int tig = lid & 3;
#pragma unroll
    for (int mt = 0; mt < 4; ++mt) {
        const int r0 = m0c + mw + mt * 16 + g;
        const int r1 = r0 + 8;
        const int pos0 = r0 & (SEQ - 1);
        const int pos1 = r1 & (SEQ - 1);
#pragma unroll
        for (int nt = 0; nt < 8; ++nt) {
            const int col = n0c + nw + nt * 8 + tig * 2;
            float d0 = acc[mt][nt][0], d1 = acc[mt][nt][1];
            float d2 = acc[mt][nt][2], d3 = acc[mt][nt][3];
            if (MODE == 1) {
                const int p = (col & 63) >> 1;
                float c0 = cosT[pos0 * 32 + p], s0 = sinT[pos0 * 32 + p];
                float c1 = cosT[pos1 * 32 + p], s1 = sinT[pos1 * 32 + p];
                float x = d0, y = d1;
                d0 = x * c0 - y * s0;  d1 = y * c0 + x * s0;
                x = d2; y = d3;
                d2 = x * c1 - y * s1;  d3 = y * c1 + x * s1;
            }
            if (MODE == 0) {
                *(float2*)(C + (size_t)r0 * DMODEL + col) = make_float2(d0, d1);
                *(float2*)(C + (size_t)r1 * DMODEL + col) = make_float2(d2, d3);
            } else {
                uint32_t h0 = packbf(d0, d1);
                uint32_t h1 = packbf(d2, d3);
                float e0 = d0 - __bfloat162float(*(__nv_bfloat16*)&h0);
                float e1 = d1 - __bfloat162float(((__nv_bfloat16*)&h0)[1]);
                float e2 = d2 - __bfloat162float(*(__nv_bfloat16*)&h1);
                float e3 = d3 - __bfloat162float(((__nv_bfloat16*)&h1)[1]);
                *(uint32_t*)(Chi + (size_t)r0 * DMODEL + col) = h0;
                *(uint32_t*)(Chi + (size_t)r1 * DMODEL + col) = h1;
                *(uint32_t*)(Clo + (size_t)r0 * DMODEL + col) = packbf(e0, e1);
                *(uint32_t*)(Clo + (size_t)r1 * DMODEL + col) = packbf(e2, e3);
            }
        }
    }
}

// ---------------------------------------------------------------------------
// Tensor-core flash attention (causal), bf16-split, mma.sync. (unchanged)
// ---------------------------------------------------------------------------
#define AO_QHI 0
#define AO_QLO 16384
#define AO_KV  32768
#define AKT    8192
#define AST    (4 * AKT)
#define ATTN_SMEM (AO_KV + 2 * AST)

__device__ __forceinline__ void attn_load_kv(
    const __nv_bfloat16* __restrict__ khi, const __nv_bfloat16* __restrict__ klo,
    const __nv_bfloat16* __restrict__ vhi, const __nv_bfloat16* __restrict__ vlo,
    size_t hbase, int kv0, uint32_t dst, int tid)
{
#pragma unroll
    for (int i = 0; i < 2; ++i) {
        int v  = tid + i * 256;
        int r  = v >> 3;
        int c8 = v & 7;
        uint32_t sw = swz128((uint32_t)(r * 128 + c8 * 16));
        size_t go = hbase + (size_t)(kv0 + r) * DMODEL + c8 * 8;
        cp16(dst + 0 * AKT + sw, khi + go);
        cp16(dst + 1 * AKT + sw, klo + go);
        cp16(dst + 2 * AKT + sw, vhi + go);
        cp16(dst + 3 * AKT + sw, vlo + go);
    }
}

__global__ __launch_bounds__(256, 1)
void attn_tc_kernel(const __nv_bfloat16* __restrict__ qhi, const __nv_bfloat16* __restrict__ qlo,
                    const __nv_bfloat16* __restrict__ khi, const __nv_bfloat16* __restrict__ klo,
                    const __nv_bfloat16* __restrict__ vhi, const __nv_bfloat16* __restrict__ vlo,
                    __nv_bfloat16* __restrict__ Ohi, __nv_bfloat16* __restrict__ Olo)
{
    extern __shared__ char sm[];
    const uint32_t sb = smem_to_u32(sm);
    const int tid = threadIdx.x;
    const int wid = tid >> 5;
    const int lid = tid & 31;
    const int qt  = (int)gridDim.x - 1 - (int)blockIdx.x;
    const int bh  = blockIdx.y;
    const int b   = bh >> 4;
    const int h   = bh & 15;
    const int q0  = qt * 128;
    const int qbase = q0 + wid * 16;

    const size_t hbase = (size_t)b * SEQ * DMODEL + (size_t)h * DK;

#pragma unroll
    for (int i = 0; i < 4; ++i) {
        int v = tid + i * 256;
        int r = v >> 3;
        int c8 = v & 7;
        uint32_t sw = swz128((uint32_t)(r * 128 + c8 * 16));
        size_t go = hbase + (size_t)(q0 + r) * DMODEL + c8 * 8;
        cp16(sb + AO_QHI + sw, qhi + go);
        cp16(sb + AO_QLO + sw, qlo + go);
    }
    cp_commit();
    attn_load_kv(khi, klo, vhi, vlo, hbase, 0, sb + AO_KV, tid);
    cp_commit();

    cp_wait1();
    __syncthreads();

    const int al  = lid & 15;
    const int ah  = lid >> 4;
    uint32_t Qh[4][4], Ql[4][4];
#pragma unroll
    for (int c = 0; c < 4; ++c) {
        uint32_t swo = swz128((uint32_t)((wid * 16 + al) * 128 + c * 32 + ah * 16));
        ldsm4(sb + AO_QHI + swo, Qh[c][0], Qh[c][1], Qh[c][2], Qh[c][3]);
        ldsm4(sb + AO_QLO + swo, Ql[c][0], Ql[c][1], Ql[c][2], Ql[c][3]);
    }

    const int g   = lid >> 2;
    const int tig = lid & 3;
    const int bl7 = lid & 7;
    const int bk  = (lid >> 3) & 1;
    const int bh8 = (lid >> 4) << 3;
    const int r0g = qbase + g;
    const int r1g = r0g + 8;

    float m0 = -1e30f, m1 = -1e30f, l0 = 0.f, l1 = 0.f;
    float o[8][4] = {};

    const int NT = 2 * qt + 2;
    for (int kt = 0; kt < NT; ++kt) {
        const int kv0 = kt * 64;
        if (kt + 1 < NT)
            attn_load_kv(khi, klo, vhi, vlo, hbase, (kt + 1) * 64,
                         sb + AO_KV + ((kt + 1) & 1) * AST, tid);
        cp_commit();
        cp_wait1();
        __syncthreads();

        if (kv0 <= qbase + 15) {
            const uint32_t base = sb + AO_KV + (kt & 1) * AST;

            float s[8][4] = {};
#pragma unroll
            for (int c = 0; c < 4; ++c) {
#pragma unroll
                for (int p = 0; p < 4; ++p) {
                    int brow = p * 16 + bl7 + bh8;
                    uint32_t swo = swz128((uint32_t)(brow * 128 + c * 32 + bk * 16));
                    uint32_t h0, h1, h2, h3, e0, e1, e2, e3;
                    ldsm4(base + 0 * AKT + swo, h0, h1, h2, h3);
                    ldsm4(base + 1 * AKT + swo, e0, e1, e2, e3);
                    const int n0 = 2 * p, n1 = 2 * p + 1;
                    mma16816(s[n0][0], s[n0][1], s[n0][2], s[n0][3],
                             Qh[c][0], Qh[c][1], Qh[c][2], Qh[c][3], h0, h1);
                    mma16816(s[n0][0], s[n0][1], s[n0][2], s[n0][3],
                             Qh[c][0], Qh[c][1], Qh[c][2], Qh[c][3], e0, e1);
                    mma16816(s[n0][0], s[n0][1], s[n0][2], s[n0][3],
                             Ql[c][0], Ql[c][1], Ql[c][2], Ql[c][3], h0, h1);
                    mma16816(s[n1][0], s[n1][1], s[n1][2], s[n1][3],
                             Qh[c][0], Qh[c][1], Qh[c][2], Qh[c][3], h2, h3);
                    mma16816(s[n1][0], s[n1][1], s[n1][2], s[n1][3],
                             Qh[c][0], Qh[c][1], Qh[c][2], Qh[c][3], e2, e3);
                    mma16816(s[n1][0], s[n1][1], s[n1][2], s[n1][3],
                             Ql[c][0], Ql[c][1], Ql[c][2], Ql[c][3], h2, h3);
                }
            }
#pragma unroll
            for (int nt = 0; nt < 8; ++nt)
#pragma unroll
                for (int j = 0; j < 4; ++j) s[nt][j] *= 0.125f;

            if (kv0 + 63 > qbase) {
#pragma unroll
                for (int nt = 0; nt < 8; ++nt) {
                    const int c0 = kv0 + nt * 8 + tig * 2;
                    if (c0     > r0g) s[nt][0] = -1e30f;
                    if (c0 + 1 > r0g) s[nt][1] = -1e30f;
                    if (c0     > r1g) s[nt][2] = -1e30f;
                    if (c0 + 1 > r1g) s[nt][3] = -1e30f;
                }
            }

            float rm0 = -1e30f, rm1 = -1e30f;
#pragma unroll
            for (int nt = 0; nt < 8; ++nt) {
                rm0 = fmaxf(rm0, fmaxf(s[nt][0], s[nt][1]));
                rm1 = fmaxf(rm1, fmaxf(s[nt][2], s[nt][3]));
            }
            rm0 = fmaxf(rm0, __shfl_xor_sync(0xffffffffu, rm0, 1));
            rm0 = fmaxf(rm0, __shfl_xor_sync(0xffffffffu, rm0, 2));
            rm1 = fmaxf(rm1, __shfl_xor_sync(0xffffffffu, rm1, 1));
            rm1 = fmaxf(rm1, __shfl_xor_sync(0xffffffffu, rm1, 2));
            const float mn0 = fmaxf(m0, rm0);
            const float mn1 = fmaxf(m1, rm1);
            const float a0  = __expf(m0 - mn0);
            const float a1  = __expf(m1 - mn1);
            float rs0 = 0.f, rs1 = 0.f;
#pragma unroll
            for (int nt = 0; nt < 8; ++nt) {
                s[nt][0] = __expf(s[nt][0] - mn0);
                s[nt][1] = __expf(s[nt][1] - mn0);
                s[nt][2] = __expf(s[nt][2] - mn1);
                s[nt][3] = __expf(s[nt][3] - mn1);
                rs0 += s[nt][0] + s[nt][1];
                rs1 += s[nt][2] + s[nt][3];
            }
            rs0 += __shfl_xor_sync(0xffffffffu, rs0, 1);
            rs0 += __shfl_xor_sync(0xffffffffu, rs0, 2);
            rs1 += __shfl_xor_sync(0xffffffffu, rs1, 1);
            rs1 += __shfl_xor_sync(0xffffffffu, rs1, 2);
            l0 = l0 * a0 + rs0;  m0 = mn0;
            l1 = l1 * a1 + rs1;  m1 = mn1;
#pragma unroll
            for (int nt = 0; nt < 8; ++nt) {
                o[nt][0] *= a0; o[nt][1] *= a0;
                o[nt][2] *= a1; o[nt][3] *= a1;
            }

            uint32_t ph[8][2], pl[8][2];
#pragma unroll
            for (int nt = 0; nt < 8; ++nt) {
                ph[nt][0] = packbf(s[nt][0], s[nt][1]);
                ph[nt][1] = packbf(s[nt][2], s[nt][3]);
                float e0 = s[nt][0] - __bfloat162float(*(__nv_bfloat16*)&ph[nt][0]);
                float e1 = s[nt][1] - __bfloat162float(((__nv_bfloat16*)&ph[nt][0])[1]);
                float e2 = s[nt][2] - __bfloat162float(*(__nv_bfloat16*)&ph[nt][1]);
                float e3 = s[nt][3] - __bfloat162float(((__nv_bfloat16*)&ph[nt][1])[1]);
                pl[nt][0] = packbf(e0, e1);
                pl[nt][1] = packbf(e2, e3);
            }

#pragma unroll
            for (int c = 0; c < 4; ++c) {
                const uint32_t A0 = ph[2*c][0],   A1 = ph[2*c][1];
                const uint32_t A2 = ph[2*c+1][0], A3 = ph[2*c+1][1];
                const uint32_t L0 = pl[2*c][0],   L1 = pl[2*c][1];
                const uint32_t L2 = pl[2*c+1][0], L3 = pl[2*c+1][1];
#pragma unroll
                for (int p = 0; p < 4; ++p) {
                    int krow = c * 16 + bl7 + bk * 8;
                    int ncol = p * 16 + (lid >> 4) * 8;
                    uint32_t swo = swz128((uint32_t)(krow * 128 + ncol * 2));
                    uint32_t h0, h1, h2, h3, e0, e1, e2, e3;
                    ldsm4t(base + 2 * AKT + swo, h0, h1, h2, h3);
                    ldsm4t(base + 3 * AKT + swo, e0, e1, e2, e3);
                    const int n0 = 2 * p, n1 = 2 * p + 1;
                    mma16816(o[n0][0], o[n0][1], o[n0][2], o[n0][3],
                             A0, A1, A2, A3, h0, h1);
                    mma16816(o[n0][0], o[n0][1], o[n0][2], o[n0][3],
                             A0, A1, A2, A3, e0, e1);
                    mma16816(o[n0][0], o[n0][1], o[n0][2], o[n0][3],
                             L0, L1, L2, L3, h0, h1);
                    mma16816(o[n1][0], o[n1][1], o[n1][2], o[n1][3],
                             A0, A1, A2, A3, h2, h3);
                    mma16816(o[n1][0], o[n1][1], o[n1][2], o[n1][3],
                             A0, A1, A2, A3, e2, e3);
                    mma16816(o[n1][0], o[n1][1], o[n1][2], o[n1][3],
                             L0, L1, L2, L3, h2, h3);
                }
            }
        }
        __syncthreads();
    }

    const float inv0 = 1.f / l0;
    const float inv1 = 1.f / l1;
#pragma unroll
    for (int nt = 0; nt < 8; ++nt) {
        const int col = nt * 8 + tig * 2;
        float d0 = o[nt][0] * inv0, d1 = o[nt][1] * inv0;
        float d2 = o[nt][2] * inv1, d3 = o[nt][3] * inv1;
        uint32_t h0 = packbf(d0, d1);
        uint32_t h1 = packbf(d2, d3);
        float e0 = d0 - __bfloat162float(*(__nv_bfloat16*)&h0);
        float e1 = d1 - __bfloat162float(((__nv_bfloat16*)&h0)[1]);
        float e2 = d2 - __bfloat162float(*(__nv_bfloat16*)&h1);
        float e3 = d3 - __bfloat162float(((__nv_bfloat16*)&h1)[1]);
        *(uint32_t*)(Ohi + hbase + (size_t)r0g * DMODEL + col) = h0;
        *(uint32_t*)(Ohi + hbase + (size_t)r1g * DMODEL + col) = h1;
        *(uint32_t*)(Olo + hbase + (size_t)r0g * DMODEL + col) = packbf(e0, e1);
        *(uint32_t*)(Olo + hbase + (size_t)r1g * DMODEL + col) = packbf(e2, e3);
    }
}

// ---------------------------------------------------------------------------
// Launch
// ---------------------------------------------------------------------------
extern "C" void kernel_launch(void* const* d_in, const int* in_sizes, int n_in,
                              void* d_out, int out_size)
{
    const float* x  = (const float*)d_in[0];
    const float* wq = (const float*)d_in[1];
    const float* wk = (const float*)d_in[2];
    const float* wv = (const float*)d_in[3];
    const float* wo = (const float*)d_in[4];
    float* out = (float*)d_out;

    float *cT, *sT;
    cudaGetSymbolAddress((void**)&cT, g_cos);
    cudaGetSymbolAddress((void**)&sT, g_sin);

    __nv_bfloat16 *xhi, *xlo, *chi, *clo, *whi, *wlo;
    __nv_bfloat16 *qh, *ql, *kh, *kl, *vh, *vl;
    cudaGetSymbolAddress((void**)&xhi, g_xhi);
    cudaGetSymbolAddress((void**)&xlo, g_xlo);
    cudaGetSymbolAddress((void**)&chi, g_chi);
    cudaGetSymbolAddress((void**)&clo, g_clo);
    cudaGetSymbolAddress((void**)&whi, g_whi);
    cudaGetSymbolAddress((void**)&wlo, g_wlo);
    cudaGetSymbolAddress((void**)&qh,  g_qhi);
    cudaGetSymbolAddress((void**)&ql,  g_qlo);
    cudaGetSymbolAddress((void**)&kh,  g_khi);
    cudaGetSymbolAddress((void**)&kl,  g_klo);
    cudaGetSymbolAddress((void**)&vh,  g_vhi);
    cudaGetSymbolAddress((void**)&vl,  g_vlo);
    const size_t WN = (size_t)DMODEL * DMODEL;

    cudaFuncSetAttribute(gemm_mma_kernel<0>,
                         cudaFuncAttributeMaxDynamicSharedMemorySize, GEMM_SMEM);
    cudaFuncSetAttribute(gemm_mma_kernel<1>,
                         cudaFuncAttributeMaxDynamicSharedMemorySize, GEMM_SMEM);
    cudaFuncSetAttribute(gemm_mma_kernel<2>,
                         cudaFuncAttributeMaxDynamicSharedMemorySize, GEMM_SMEM);
    cudaFuncSetAttribute(attn_tc_kernel,
                         cudaFuncAttributeMaxDynamicSharedMemorySize, ATTN_SMEM);

    rope_table_kernel<<<(SEQ * 32 + 255) / 256, 256>>>(cT, sT);

    const int xN4 = NTOK * DMODEL / 4;
    const int wN4 = DMODEL * DMODEL / 4;
    split_bf16_kernel<<<(xN4 + 255) / 256, 256>>>(x, xhi, xlo, xN4);
    split_w4_kernel<<<dim3((wN4 + 255) / 256, 4), 256>>>(wq, wk, wv, wo, whi, wlo, wN4);

    dim3 gg(DMODEL / TN, NTOK / TM);   // (4, 32) = 128 CTAs, one wave
    gemm_mma_kernel<1><<<gg, 256, GEMM_SMEM>>>(xhi, xlo, whi + 0 * WN, wlo + 0 * WN,
                                               nullptr, qh, ql, cT, sT);
    gemm_mma_kernel<1><<<gg, 256, GEMM_SMEM>>>(xhi, xlo, whi + 1 * WN, wlo + 1 * WN,
                                               nullptr, kh, kl, cT, sT);
    gemm_mma_kernel<2><<<gg, 256, GEMM_SMEM>>>(xhi, xlo, whi + 2 * WN, wlo + 2 * WN,
                                               nullptr, vh, vl, cT, sT);

    attn_tc_kernel<<<dim3(SEQ / 128, BATCH * HEADS), 256, ATTN_SMEM>>>(
        qh, ql, kh, kl, vh, vl, chi, clo);

    gemm_mma_kernel<0><<<gg, 256, GEMM_SMEM>>>(chi, clo, whi + 3 * WN, wlo + 3 * WN,
                                               out, nullptr, nullptr, cT, sT);
}

// round 16
// speedup vs baseline: 1.0289x; 1.0041x over previous
#include <cuda_runtime.h>
#include <cuda_bf16.h>
#include <math.h>
#include <stdint.h>

// ---------------------------------------------------------------------------
// Problem constants
// ---------------------------------------------------------------------------
#define BATCH   2
#define SEQ     2048
#define DMODEL  1024
#define HEADS   16
#define DK      64
#define NTOK    (BATCH * SEQ)        // 4096

// ---------------------------------------------------------------------------
// Scratch (device globals — no allocation allowed)
// ---------------------------------------------------------------------------
__device__ __align__(256) float g_cos[SEQ * (DK / 2)];
__device__ __align__(256) float g_sin[SEQ * (DK / 2)];

__device__ __align__(256) __nv_bfloat16 g_xhi[(size_t)NTOK * DMODEL];
__device__ __align__(256) __nv_bfloat16 g_xlo[(size_t)NTOK * DMODEL];
__device__ __align__(256) __nv_bfloat16 g_chi[(size_t)NTOK * DMODEL];
__device__ __align__(256) __nv_bfloat16 g_clo[(size_t)NTOK * DMODEL];
__device__ __align__(256) __nv_bfloat16 g_whi[4][(size_t)DMODEL * DMODEL];
__device__ __align__(256) __nv_bfloat16 g_wlo[4][(size_t)DMODEL * DMODEL];
__device__ __align__(256) __nv_bfloat16 g_qhi[(size_t)NTOK * DMODEL];
__device__ __align__(256) __nv_bfloat16 g_qlo[(size_t)NTOK * DMODEL];
__device__ __align__(256) __nv_bfloat16 g_khi[(size_t)NTOK * DMODEL];
__device__ __align__(256) __nv_bfloat16 g_klo[(size_t)NTOK * DMODEL];
__device__ __align__(256) __nv_bfloat16 g_vhi[(size_t)NTOK * DMODEL];
__device__ __align__(256) __nv_bfloat16 g_vlo[(size_t)NTOK * DMODEL];

// ---------------------------------------------------------------------------
// Generic-PTX helpers (sm_80+/sm_75+; safe for compute_103 target)
// ---------------------------------------------------------------------------
__device__ __forceinline__ uint32_t smem_to_u32(const void* p) {
    uint32_t a;
    asm("{ .reg .u64 t; cvta.to.shared.u64 t, %1; cvt.u32.u64 %0, t; }" : "=r"(a) : "l"(p));
    return a;
}
__device__ __forceinline__ uint32_t swz128(uint32_t bo) { return bo ^ ((bo >> 3) & 0x70); }

__device__ __forceinline__ void cp16(uint32_t dst, const void* src) {
    asm volatile("cp.async.cg.shared.global [%0], [%1], 16;" :: "r"(dst), "l"(src) : "memory");
}
__device__ __forceinline__ void cp_commit() { asm volatile("cp.async.commit_group;" ::: "memory"); }
__device__ __forceinline__ void cp_wait1()  { asm volatile("cp.async.wait_group 1;"  ::: "memory"); }

__device__ __forceinline__ void ldsm4(uint32_t addr, uint32_t& r0, uint32_t& r1,
                                      uint32_t& r2, uint32_t& r3) {
    asm volatile("ldmatrix.sync.aligned.m8n8.x4.shared.b16 {%0,%1,%2,%3}, [%4];"
                 : "=r"(r0), "=r"(r1), "=r"(r2), "=r"(r3) : "r"(addr));
}
__device__ __forceinline__ void ldsm4t(uint32_t addr, uint32_t& r0, uint32_t& r1,
                                       uint32_t& r2, uint32_t& r3) {
    asm volatile("ldmatrix.sync.aligned.m8n8.x4.trans.shared.b16 {%0,%1,%2,%3}, [%4];"
                 : "=r"(r0), "=r"(r1), "=r"(r2), "=r"(r3) : "r"(addr));
}
__device__ __forceinline__ void mma16816(float& c0, float& c1, float& c2, float& c3,
                                         uint32_t a0, uint32_t a1, uint32_t a2, uint32_t a3,
                                         uint32_t b0, uint32_t b1) {
    asm volatile("mma.sync.aligned.m16n8k16.row.col.f32.bf16.bf16.f32 "
                 "{%0,%1,%2,%3}, {%4,%5,%6,%7}, {%8,%9}, {%0,%1,%2,%3};"
                 : "+f"(c0), "+f"(c1), "+f"(c2), "+f"(c3)
                 : "r"(a0), "r"(a1), "r"(a2), "r"(a3), "r"(b0), "r"(b1));
}
__device__ __forceinline__ uint32_t packbf(float x, float y) {
    __nv_bfloat162 t = __halves2bfloat162(__float2bfloat16_rn(x), __float2bfloat16_rn(y));
    return *reinterpret_cast<uint32_t*>(&t);
}

// ---------------------------------------------------------------------------
// RoPE table
// ---------------------------------------------------------------------------
__global__ void rope_table_kernel(float* __restrict__ cosT, float* __restrict__ sinT)
{
    int idx = blockIdx.x * blockDim.x + threadIdx.x;
    if (idx >= SEQ * (DK / 2)) return;
    int s = idx >> 5;
    int i = idx & 31;
    double inv = pow(10000.0, -((double)(2 * i) / (double)DK));
    float  invf = (float)inv;
    float  ang  = (float)s * invf;
    cosT[idx] = (float)cos((double)ang);
    sinT[idx] = (float)sin((double)ang);
}

// ---------------------------------------------------------------------------
// fp32 -> bf16 hi/lo split
// ---------------------------------------------------------------------------
__device__ __forceinline__ void split4(const float* __restrict__ src,
                                       __nv_bfloat16* __restrict__ hi,
                                       __nv_bfloat16* __restrict__ lo, int i)
{
    float4 a = ((const float4*)src)[i];
    __nv_bfloat16 h0 = __float2bfloat16_rn(a.x);
    __nv_bfloat16 h1 = __float2bfloat16_rn(a.y);
    __nv_bfloat16 h2 = __float2bfloat16_rn(a.z);
    __nv_bfloat16 h3 = __float2bfloat16_rn(a.w);
    __nv_bfloat16 l0 = __float2bfloat16_rn(a.x - __bfloat162float(h0));
    __nv_bfloat16 l1 = __float2bfloat16_rn(a.y - __bfloat162float(h1));
    __nv_bfloat16 l2 = __float2bfloat16_rn(a.z - __bfloat162float(h2));
    __nv_bfloat16 l3 = __float2bfloat16_rn(a.w - __bfloat162float(h3));
    __nv_bfloat162* hp = (__nv_bfloat162*)hi;
    __nv_bfloat162* lp = (__nv_bfloat162*)lo;
    hp[2 * i]     = __halves2bfloat162(h0, h1);
    hp[2 * i + 1] = __halves2bfloat162(h2, h3);
    lp[2 * i]     = __halves2bfloat162(l0, l1);
    lp[2 * i + 1] = __halves2bfloat162(l2, l3);
}

__global__ void split_bf16_kernel(const float* __restrict__ src,
                                  __nv_bfloat16* __restrict__ hi,
                                  __nv_bfloat16* __restrict__ lo, int n4)
{
    int i = blockIdx.x * blockDim.x + threadIdx.x;
    if (i < n4) split4(src, hi, lo, i);
}

__global__ void split_w4_kernel(const float* __restrict__ w0, const float* __restrict__ w1,
                                const float* __restrict__ w2, const float* __restrict__ w3,
                                __nv_bfloat16* __restrict__ hi, __nv_bfloat16* __restrict__ lo,
                                int n4)
{
    int i = blockIdx.x * blockDim.x + threadIdx.x;
    if (i >= n4) return;
    const float* src = (blockIdx.y == 0) ? w0 : (blockIdx.y == 1) ? w1
                      : (blockIdx.y == 2) ? w2 : w3;
    size_t off = (size_t)blockIdx.y * DMODEL * DMODEL;
    split4(src, hi + off, lo + off, i);
}

// ---------------------------------------------------------------------------
// mma.sync bf16-split GEMM:  C[M,N] = A[M,K] * B[N,K]^T  (hh + hl + lh)
// CTA 128x256, BK=64, SW128 smem, 2-stage cp.async pipeline, 128 CTAs = 1 wave.
// 512 threads / 16 warps as 2(M) x 8(N); warp tile 64x32 = 4x4 m16n8 tiles
// -> 64 acc regs/thread, no spill, 4 warps per SMSP.
// MODE 0: fp32 output. MODE 1: bf16 hi/lo + RoPE. MODE 2: bf16 hi/lo.
// ---------------------------------------------------------------------------
#define TM 128
#define TN 256
#define KC 64
#define NKC (DMODEL / KC)                 // 16
#define GEMM_THREADS 512
#define A_TB (TM * KC * 2)                // 16384
#define B_TB (TN * KC * 2)                // 32768
#define OFF_AHI 0
#define OFF_ALO (A_TB)
#define OFF_BHI (2 * A_TB)
#define OFF_BLO (2 * A_TB + B_TB)
#define STG_BYTES (2 * A_TB + 2 * B_TB)   // 98304
#define GEMM_SMEM (2 * STG_BYTES)         // 196608

__device__ __forceinline__ void stage_load(
    const __nv_bfloat16* __restrict__ Ahi, const __nv_bfloat16* __restrict__ Alo,
    const __nv_bfloat16* __restrict__ Bhi, const __nv_bfloat16* __restrict__ Blo,
    int m0, int n0, int k0, uint32_t sbase, int tid)
{
#pragma unroll
    for (int i = 0; i < 2; ++i) {          // A: 1024 vectors / 512 thr
        int v  = tid + i * GEMM_THREADS;
        int r  = v >> 3;
        int c8 = v & 7;
        uint32_t sw = swz128((uint32_t)(r * 128 + c8 * 16));
        size_t go = (size_t)(m0 + r) * DMODEL + k0 + c8 * 8;
        cp16(sbase + OFF_AHI + sw, Ahi + go);
        cp16(sbase + OFF_ALO + sw, Alo + go);
    }
#pragma unroll
    for (int i = 0; i < 4; ++i) {          // B: 2048 vectors / 512 thr
        int v  = tid + i * GEMM_THREADS;
        int r  = v >> 3;
        int c8 = v & 7;
        uint32_t sw = swz128((uint32_t)(r * 128 + c8 * 16));
        size_t go = (size_t)(n0 + r) * DMODEL + k0 + c8 * 8;
        cp16(sbase + OFF_BHI + sw, Bhi + go);
        cp16(sbase + OFF_BLO + sw, Blo + go);
    }
}

template<int MODE>
__global__ __launch_bounds__(GEMM_THREADS, 1)
void gemm_mma_kernel(const __nv_bfloat16* __restrict__ Ahi, const __nv_bfloat16* __restrict__ Alo,
                     const __nv_bfloat16* __restrict__ Bhi, const __nv_bfloat16* __restrict__ Blo,
                     float* __restrict__ C,
                     __nv_bfloat16* __restrict__ Chi, __nv_bfloat16* __restrict__ Clo,
                     const float* __restrict__ cosT, const float* __restrict__ sinT)
{
    extern __shared__ char sm[];
    const uint32_t sb = smem_to_u32(sm);
    const int tid = threadIdx.x;
    const int wid = tid >> 5;
    const int lid = tid & 31;
    const int mw  = (wid & 1) * 64;       // 2 warps in M
    const int nw  = (wid >> 1) * 32;      // 8 warps in N
    const int m0c = blockIdx.y * TM;
    const int n0c = blockIdx.x * TN;

    float acc[4][4][4] = {};

    stage_load(Ahi, Alo, Bhi, Blo, m0c, n0c, 0, sb, tid);
    cp_commit();

    const int al  = lid & 15;
    const int ah  = lid >> 4;
    const int bl7 = lid & 7;
    const int bk  = (lid >> 3) & 1;
    const int bh8 = (lid >> 4) << 3;

    for (int kc = 0; kc < NKC; ++kc) {
        if (kc + 1 < NKC)
            stage_load(Ahi, Alo, Bhi, Blo, m0c, n0c, (kc + 1) * KC,
                       sb + ((kc + 1) & 1) * STG_BYTES, tid);
        cp_commit();
        cp_wait1();
        __syncthreads();

        const uint32_t base = sb + (kc & 1) * STG_BYTES;
#pragma unroll
        for (int c = 0; c < 4; ++c) {
            uint32_t bh[4][2], bl[4][2];
#pragma unroll
            for (int p = 0; p < 2; ++p) {          // 2 pairs of n8 tiles (32 cols)
                int brow = nw + p * 16 + bl7 + bh8;
                uint32_t swo = swz128((uint32_t)(brow * 128 + c * 32 + bk * 16));
                uint32_t q0, q1, q2, q3;
                ldsm4(base + OFF_BHI + swo, q0, q1, q2, q3);
                bh[p*2][0] = q0; bh[p*2][1] = q1; bh[p*2+1][0] = q2; bh[p*2+1][1] = q3;
                ldsm4(base + OFF_BLO + swo, q0, q1, q2, q3);
                bl[p*2][0] = q0; bl[p*2][1] = q1; bl[p*2+1][0] = q2; bl[p*2+1][1] = q3;
            }
            uint32_t a[4][4];
#pragma unroll
            for (int mt = 0; mt < 4; ++mt) {
                int arow = mw + mt * 16 + al;
                uint32_t swo = swz128((uint32_t)(arow * 128 + c * 32 + ah * 16));
                ldsm4(base + OFF_AHI + swo, a[mt][0], a[mt][1], a[mt][2], a[mt][3]);
            }
#pragma unroll
            for (int mt = 0; mt < 4; ++mt)
#pragma unroll
                for (int nt = 0; nt < 4; ++nt) {
                    mma16816(acc[mt][nt][0], acc[mt][nt][1], acc[mt][nt][2], acc[mt][nt][3],
                             a[mt][0], a[mt][1], a[mt][2], a[mt][3], bh[nt][0], bh[nt][1]);
                    mma16816(acc[mt][nt][0], acc[mt][nt][1], acc[mt][nt][2], acc[mt][nt][3],
                             a[mt][0], a[mt][1], a[mt][2], a[mt][3], bl[nt][0], bl[nt][1]);
                }
#pragma unroll
            for (int mt = 0; mt < 4; ++mt) {
                int arow = mw + mt * 16 + al;
                uint32_t swo = swz128((uint32_t)(arow * 128 + c * 32 + ah * 16));
                ldsm4(base + OFF_ALO + swo, a[mt][0], a[mt][1], a[mt][2], a[mt][3]);
            }
#pragma unroll
            for (int mt = 0; mt < 4; ++mt)
#pragma unroll
                for (int nt = 0; nt < 4; ++nt)
                    mma16816(acc[mt][nt][0], acc[mt][nt][1], acc[mt][nt][2], acc[mt][nt][3],
                             a[mt][0], a[mt][1], a[mt][2], a[mt][3], bh[nt][0], bh[nt][1]);
        }
        __syncthreads();
    }

    // epilogue
    const int g   = lid >> 2;
    const int tig = lid & 3;
#pragma unroll
    for (int mt = 0; mt < 4; ++mt) {
        const int r0 = m0c + mw + mt * 16 + g;
        const int r1 = r0 + 8;
        const int pos0 = r0 & (SEQ - 1);
        const int pos1 = r1 & (SEQ - 1);
#pragma unroll
        for (int nt = 0; nt < 4; ++nt) {
            const int col = n0c + nw + nt * 8 + tig * 2;
            float d0 = acc[mt][nt][0], d1 = acc[mt][nt][1];
            float d2 = acc[mt][nt][2], d3 = acc[mt][nt][3];
            if (MODE == 1) {
                const int p = (col & 63) >> 1;
                float c0 = cosT[pos0 * 32 + p], s0 = sinT[pos0 * 32 + p];
                float c1 = cosT[pos1 * 32 + p], s1 = sinT[pos1 * 32 + p];
                float x = d0, y = d1;
                d0 = x * c0 - y * s0;  d1 = y * c0 + x * s0;
                x = d2; y = d3;
                d2 = x * c1 - y * s1;  d3 = y * c1 + x * s1;
            }
            if (MODE == 0) {
                *(float2*)(C + (size_t)r0 * DMODEL + col) = make_float2(d0, d1);
                *(float2*)(C + (size_t)r1 * DMODEL + col) = make_float2(d2, d3);
            } else {
                uint32_t h0 = packbf(d0, d1);
                uint32_t h1 = packbf(d2, d3);
                float e0 = d0 - __bfloat162float(*(__nv_bfloat16*)&h0);
                float e1 = d1 - __bfloat162float(((__nv_bfloat16*)&h0)[1]);
                float e2 = d2 - __bfloat162float(*(__nv_bfloat16*)&h1);
                float e3 = d3 - __bfloat162float(((__nv_bfloat16*)&h1)[1]);
                *(uint32_t*)(Chi + (size_t)r0 * DMODEL + col) = h0;
                *(uint32_t*)(Chi + (size_t)r1 * DMODEL + col) = h1;
                *(uint32_t*)(Clo + (size_t)r0 * DMODEL + col) = packbf(e0, e1);
                *(uint32_t*)(Clo + (size_t)r1 * DMODEL + col) = packbf(e2, e3);
            }
        }
    }
}

// ---------------------------------------------------------------------------
// Tensor-core flash attention (causal), bf16-split, mma.sync. (unchanged)
// ---------------------------------------------------------------------------
#define AO_QHI 0
#define AO_QLO 16384
#define AO_KV  32768
#define AKT    8192
#define AST    (4 * AKT)
#define ATTN_SMEM (AO_KV + 2 * AST)

__device__ __forceinline__ void attn_load_kv(
    const __nv_bfloat16* __restrict__ khi, const __nv_bfloat16* __restrict__ klo,
    const __nv_bfloat16* __restrict__ vhi, const __nv_bfloat16* __restrict__ vlo,
    size_t hbase, int kv0, uint32_t dst, int tid)
{
#pragma unroll
    for (int i = 0; i < 2; ++i) {
        int v  = tid + i * 256;
        int r  = v >> 3;
        int c8 = v & 7;
        uint32_t sw = swz128((uint32_t)(r * 128 + c8 * 16));
        size_t go = hbase + (size_t)(kv0 + r) * DMODEL + c8 * 8;
        cp16(dst + 0 * AKT + sw, khi + go);
        cp16(dst + 1 * AKT + sw, klo + go);
        cp16(dst + 2 * AKT + sw, vhi + go);
        cp16(dst + 3 * AKT + sw, vlo + go);
    }
}

__global__ __launch_bounds__(256, 1)
void attn_tc_kernel(const __nv_bfloat16* __restrict__ qhi, const __nv_bfloat16* __restrict__ qlo,
                    const __nv_bfloat16* __restrict__ khi, const __nv_bfloat16* __restrict__ klo,
                    const __nv_bfloat16* __restrict__ vhi, const __nv_bfloat16* __restrict__ vlo,
                    __nv_bfloat16* __restrict__ Ohi, __nv_bfloat16* __restrict__ Olo)
{
    extern __shared__ char sm[];
    const uint32_t sb = smem_to_u32(sm);
    const int tid = threadIdx.x;
    const int wid = tid >> 5;
    const int lid = tid & 31;
    const int qt  = (int)gridDim.x - 1 - (int)blockIdx.x;
    const int bh  = blockIdx.y;
    const int b   = bh >> 4;
    const int h   = bh & 15;
    const int q0  = qt * 128;
    const int qbase = q0 + wid * 16;

    const size_t hbase = (size_t)b * SEQ * DMODEL + (size_t)h * DK;

#pragma unroll
    for (int i = 0; i < 4; ++i) {
        int v = tid + i * 256;
        int r = v >> 3;
        int c8 = v & 7;
        uint32_t sw = swz128((uint32_t)(r * 128 + c8 * 16));
        size_t go = hbase + (size_t)(q0 + r) * DMODEL + c8 * 8;
        cp16(sb + AO_QHI + sw, qhi + go);
        cp16(sb + AO_QLO + sw, qlo + go);
    }
    cp_commit();
    attn_load_kv(khi, klo, vhi, vlo, hbase, 0, sb + AO_KV, tid);
    cp_commit();

    cp_wait1();
    __syncthreads();

    const int al  = lid & 15;
    const int ah  = lid >> 4;
    uint32_t Qh[4][4], Ql[4][4];
#pragma unroll
    for (int c = 0; c < 4; ++c) {
        uint32_t swo = swz128((uint32_t)((wid * 16 + al) * 128 + c * 32 + ah * 16));
        ldsm4(sb + AO_QHI + swo, Qh[c][0], Qh[c][1], Qh[c][2], Qh[c][3]);
        ldsm4(sb + AO_QLO + swo, Ql[c][0], Ql[c][1], Ql[c][2], Ql[c][3]);
    }

    const int g   = lid >> 2;
    const int tig = lid & 3;
    const int bl7 = lid & 7;
    const int bk  = (lid >> 3) & 1;
    const int bh8 = (lid >> 4) << 3;
    const int r0g = qbase + g;
    const int r1g = r0g + 8;

    float m0 = -1e30f, m1 = -1e30f, l0 = 0.f, l1 = 0.f;
    float o[8][4] = {};

    const int NT = 2 * qt + 2;
    for (int kt = 0; kt < NT; ++kt) {
        const int kv0 = kt * 64;
        if (kt + 1 < NT)
            attn_load_kv(khi, klo, vhi, vlo, hbase, (kt + 1) * 64,
                         sb + AO_KV + ((kt + 1) & 1) * AST, tid);
        cp_commit();
        cp_wait1();
        __syncthreads();

        if (kv0 <= qbase + 15) {
            const uint32_t base = sb + AO_KV + (kt & 1) * AST;

            float s[8][4] = {};
#pragma unroll
            for (int c = 0; c < 4; ++c) {
#pragma unroll
                for (int p = 0; p < 4; ++p) {
                    int brow = p * 16 + bl7 + bh8;
                    uint32_t swo = swz128((uint32_t)(brow * 128 + c * 32 + bk * 16));
                    uint32_t h0, h1, h2, h3, e0, e1, e2, e3;
                    ldsm4(base + 0 * AKT + swo, h0, h1, h2, h3);
                    ldsm4(base + 1 * AKT + swo, e0, e1, e2, e3);
                    const int n0 = 2 * p, n1 = 2 * p + 1;
                    mma16816(s[n0][0], s[n0][1], s[n0][2], s[n0][3],
                             Qh[c][0], Qh[c][1], Qh[c][2], Qh[c][3], h0, h1);
                    mma16816(s[n0][0], s[n0][1], s[n0][2], s[n0][3],
                             Qh[c][0], Qh[c][1], Qh[c][2], Qh[c][3], e0, e1);
                    mma16816(s[n0][0], s[n0][1], s[n0][2], s[n0][3],
                             Ql[c][0], Ql[c][1], Ql[c][2], Ql[c][3], h0, h1);
                    mma16816(s[n1][0], s[n1][1], s[n1][2], s[n1][3],
                             Qh[c][0], Qh[c][1], Qh[c][2], Qh[c][3], h2, h3);
                    mma16816(s[n1][0], s[n1][1], s[n1][2], s[n1][3],
                             Qh[c][0], Qh[c][1], Qh[c][2], Qh[c][3], e2, e3);
                    mma16816(s[n1][0], s[n1][1], s[n1][2], s[n1][3],
                             Ql[c][0], Ql[c][1], Ql[c][2], Ql[c][3], h2, h3);
                }
            }
#pragma unroll
            for (int nt = 0; nt < 8; ++nt)
#pragma unroll
                for (int j = 0; j < 4; ++j) s[nt][j] *= 0.125f;

            if (kv0 + 63 > qbase) {
#pragma unroll
                for (int nt = 0; nt < 8; ++nt) {
                    const int c0 = kv0 + nt * 8 + tig * 2;
                    if (c0     > r0g) s[nt][0] = -1e30f;
                    if (c0 + 1 > r0g) s[nt][1] = -1e30f;
                    if (c0     > r1g) s[nt][2] = -1e30f;
                    if (c0 + 1 > r1g) s[nt][3] = -1e30f;
                }
            }

            float rm0 = -1e30f, rm1 = -1e30f;
#pragma unroll
            for (int nt = 0; nt < 8; ++nt) {
                rm0 = fmaxf(rm0, fmaxf(s[nt][0], s[nt][1]));
                rm1 = fmaxf(rm1, fmaxf(s[nt][2], s[nt][3]));
            }
            rm0 = fmaxf(rm0, __shfl_xor_sync(0xffffffffu, rm0, 1));
            rm0 = fmaxf(rm0, __shfl_xor_sync(0xffffffffu, rm0, 2));
            rm1 = fmaxf(rm1, __shfl_xor_sync(0xffffffffu, rm1, 1));
            rm1 = fmaxf(rm1, __shfl_xor_sync(0xffffffffu, rm1, 2));
            const float mn0 = fmaxf(m0, rm0);
            const float mn1 = fmaxf(m1, rm1);
            const float a0  = __expf(m0 - mn0);
            const float a1  = __expf(m1 - mn1);
            float rs0 = 0.f, rs1 = 0.f;
#pragma unroll
            for (int nt = 0; nt < 8; ++nt) {
                s[nt][0] = __expf(s[nt][0] - mn0);
                s[nt][1] = __expf(s[nt][1] - mn0);
                s[nt][2] = __expf(s[nt][2] - mn1);
                s[nt][3] = __expf(s[nt][3] - mn1);
                rs0 += s[nt][0] + s[nt][1];
                rs1 += s[nt][2] + s[nt][3];
            }
            rs0 += __shfl_xor_sync(0xffffffffu, rs0, 1);
            rs0 += __shfl_xor_sync(0xffffffffu, rs0, 2);
            rs1 += __shfl_xor_sync(0xffffffffu, rs1, 1);
            rs1 += __shfl_xor_sync(0xffffffffu, rs1, 2);
            l0 = l0 * a0 + rs0;  m0 = mn0;
            l1 = l1 * a1 + rs1;  m1 = mn1;
#pragma unroll
            for (int nt = 0; nt < 8; ++nt) {
                o[nt][0] *= a0; o[nt][1] *= a0;
                o[nt][2] *= a1; o[nt][3] *= a1;
            }

            uint32_t ph[8][2], pl[8][2];
#pragma unroll
            for (int nt = 0; nt < 8; ++nt) {
                ph[nt][0] = packbf(s[nt][0], s[nt][1]);
                ph[nt][1] = packbf(s[nt][2], s[nt][3]);
                float e0 = s[nt][0] - __bfloat162float(*(__nv_bfloat16*)&ph[nt][0]);
                float e1 = s[nt][1] - __bfloat162float(((__nv_bfloat16*)&ph[nt][0])[1]);
                float e2 = s[nt][2] - __bfloat162float(*(__nv_bfloat16*)&ph[nt][1]);
                float e3 = s[nt][3] - __bfloat162float(((__nv_bfloat16*)&ph[nt][1])[1]);
                pl[nt][0] = packbf(e0, e1);
                pl[nt][1] = packbf(e2, e3);
            }

#pragma unroll
            for (int c = 0; c < 4; ++c) {
                const uint32_t A0 = ph[2*c][0],   A1 = ph[2*c][1];
                const uint32_t A2 = ph[2*c+1][0], A3 = ph[2*c+1][1];
                const uint32_t L0 = pl[2*c][0],   L1 = pl[2*c][1];
                const uint32_t L2 = pl[2*c+1][0], L3 = pl[2*c+1][1];
#pragma unroll
                for (int p = 0; p < 4; ++p) {
                    int krow = c * 16 + bl7 + bk * 8;
                    int ncol = p * 16 + (lid >> 4) * 8;
                    uint32_t swo = swz128((uint32_t)(krow * 128 + ncol * 2));
                    uint32_t h0, h1, h2, h3, e0, e1, e2, e3;
                    ldsm4t(base + 2 * AKT + swo, h0, h1, h2, h3);
                    ldsm4t(base + 3 * AKT + swo, e0, e1, e2, e3);
                    const int n0 = 2 * p, n1 = 2 * p + 1;
                    mma16816(o[n0][0], o[n0][1], o[n0][2], o[n0][3],
                             A0, A1, A2, A3, h0, h1);
                    mma16816(o[n0][0], o[n0][1], o[n0][2], o[n0][3],
                             A0, A1, A2, A3, e0, e1);
                    mma16816(o[n0][0], o[n0][1], o[n0][2], o[n0][3],
                             L0, L1, L2, L3, h0, h1);
                    mma16816(o[n1][0], o[n1][1], o[n1][2], o[n1][3],
                             A0, A1, A2, A3, h2, h3);
                    mma16816(o[n1][0], o[n1][1], o[n1][2], o[n1][3],
                             A0, A1, A2, A3, e2, e3);
                    mma16816(o[n1][0], o[n1][1], o[n1][2], o[n1][3],
                             L0, L1, L2, L3, h2, h3);
                }
            }
        }
        __syncthreads();
    }

    const float inv0 = 1.f / l0;
    const float inv1 = 1.f / l1;
#pragma unroll
    for (int nt = 0; nt < 8; ++nt) {
        const int col = nt * 8 + tig * 2;
        float d0 = o[nt][0] * inv0, d1 = o[nt][1] * inv0;
        float d2 = o[nt][2] * inv1, d3 = o[nt][3] * inv1;
        uint32_t h0 = packbf(d0, d1);
        uint32_t h1 = packbf(d2, d3);
        float e0 = d0 - __bfloat162float(*(__nv_bfloat16*)&h0);
        float e1 = d1 - __bfloat162float(((__nv_bfloat16*)&h0)[1]);
        float e2 = d2 - __bfloat162float(*(__nv_bfloat16*)&h1);
        float e3 = d3 - __bfloat162float(((__nv_bfloat16*)&h1)[1]);
        *(uint32_t*)(Ohi + hbase + (size_t)r0g * DMODEL + col) = h0;
        *(uint32_t*)(Ohi + hbase + (size_t)r1g * DMODEL + col) = h1;
        *(uint32_t*)(Olo + hbase + (size_t)r0g * DMODEL + col) = packbf(e0, e1);
        *(uint32_t*)(Olo + hbase + (size_t)r1g * DMODEL + col) = packbf(e2, e3);
    }
}

// ---------------------------------------------------------------------------
// Launch
// ---------------------------------------------------------------------------
extern "C" void kernel_launch(void* const* d_in, const int* in_sizes, int n_in,
                              void* d_out, int out_size)
{
    const float* x  = (const float*)d_in[0];
    const float* wq = (const float*)d_in[1];
    const float* wk = (const float*)d_in[2];
    const float* wv = (const float*)d_in[3];
    const float* wo = (const float*)d_in[4];
    float* out = (float*)d_out;

    float *cT, *sT;
    cudaGetSymbolAddress((void**)&cT, g_cos);
    cudaGetSymbolAddress((void**)&sT, g_sin);

    __nv_bfloat16 *xhi, *xlo, *chi, *clo, *whi, *wlo;
    __nv_bfloat16 *qh, *ql, *kh, *kl, *vh, *vl;
    cudaGetSymbolAddress((void**)&xhi, g_xhi);
    cudaGetSymbolAddress((void**)&xlo, g_xlo);
    cudaGetSymbolAddress((void**)&chi, g_chi);
    cudaGetSymbolAddress((void**)&clo, g_clo);
    cudaGetSymbolAddress((void**)&whi, g_whi);
    cudaGetSymbolAddress((void**)&wlo, g_wlo);
    cudaGetSymbolAddress((void**)&qh,  g_qhi);
    cudaGetSymbolAddress((void**)&ql,  g_qlo);
    cudaGetSymbolAddress((void**)&kh,  g_khi);
    cudaGetSymbolAddress((void**)&kl,  g_klo);
    cudaGetSymbolAddress((void**)&vh,  g_vhi);
    cudaGetSymbolAddress((void**)&vl,  g_vlo);
    const size_t WN = (size_t)DMODEL * DMODEL;

    cudaFuncSetAttribute(gemm_mma_kernel<0>,
                         cudaFuncAttributeMaxDynamicSharedMemorySize, GEMM_SMEM);
    cudaFuncSetAttribute(gemm_mma_kernel<1>,
                         cudaFuncAttributeMaxDynamicSharedMemorySize, GEMM_SMEM);
    cudaFuncSetAttribute(gemm_mma_kernel<2>,
                         cudaFuncAttributeMaxDynamicSharedMemorySize, GEMM_SMEM);
    cudaFuncSetAttribute(attn_tc_kernel,
                         cudaFuncAttributeMaxDynamicSharedMemorySize, ATTN_SMEM);

    rope_table_kernel<<<(SEQ * 32 + 255) / 256, 256>>>(cT, sT);

    const int xN4 = NTOK * DMODEL / 4;
    const int wN4 = DMODEL * DMODEL / 4;
    split_bf16_kernel<<<(xN4 + 255) / 256, 256>>>(x, xhi, xlo, xN4);
    split_w4_kernel<<<dim3((wN4 + 255) / 256, 4), 256>>>(wq, wk, wv, wo, whi, wlo, wN4);

    dim3 gg(DMODEL / TN, NTOK / TM);   // (4, 32) = 128 CTAs, one wave
    gemm_mma_kernel<1><<<gg, GEMM_THREADS, GEMM_SMEM>>>(xhi, xlo, whi + 0 * WN, wlo + 0 * WN,
                                                        nullptr, qh, ql, cT, sT);
    gemm_mma_kernel<1><<<gg, GEMM_THREADS, GEMM_SMEM>>>(xhi, xlo, whi + 1 * WN, wlo + 1 * WN,
                                                        nullptr, kh, kl, cT, sT);
    gemm_mma_kernel<2><<<gg, GEMM_THREADS, GEMM_SMEM>>>(xhi, xlo, whi + 2 * WN, wlo + 2 * WN,
                                                        nullptr, vh, vl, cT, sT);

    attn_tc_kernel<<<dim3(SEQ / 128, BATCH * HEADS), 256, ATTN_SMEM>>>(
        qh, ql, kh, kl, vh, vl, chi, clo);

    gemm_mma_kernel<0><<<gg, GEMM_THREADS, GEMM_SMEM>>>(chi, clo, whi + 3 * WN, wlo + 3 * WN,
                                                        out, nullptr, nullptr, cT, sT);
}